// round 6
// baseline (speedup 1.0000x reference)
#include <cuda_runtime.h>
#include <cuda_bf16.h>
#include <cstdint>

#define NB 16
#define SS 128
#define DK 128
#define NC 100
#define CSZ 8
#define RPC 16          // padded rows per CTA (13 real + 3 pad), 4 per quarter-group

// ---------------- scratch (device globals; no allocation) ----------------
__device__ float g_AL[NB * SS * DK];
__device__ float g_P23[(SS - 1) * NB * 256];
__device__ float g_P4it[(SS - 1) * NB * DK];
__device__ float g_P5[(SS - 1) * NB * DK];
__device__ float g_HT[(SS - 1) * NB * DK];
__device__ float g_W1csum[DK];

// ---------------- helpers ----------------
__device__ __forceinline__ uint32_t smem_u32(const void* p) {
    uint32_t a;
    asm("{ .reg .u64 t; cvta.to.shared.u64 t, %1; cvt.u32.u64 %0, t; }"
        : "=r"(a) : "l"(p));
    return a;
}
__device__ __forceinline__ uint32_t mapa_u32(uint32_t addr, uint32_t rank) {
    uint32_t ra;
    asm("mapa.shared::cluster.u32 %0, %1, %2;" : "=r"(ra) : "r"(addr), "r"(rank));
    return ra;
}
__device__ __forceinline__ void mbar_init(uint32_t mbar, uint32_t cnt) {
    asm volatile("mbarrier.init.shared.b64 [%0], %1;" :: "r"(mbar), "r"(cnt) : "memory");
}
__device__ __forceinline__ void mbar_expect(uint32_t mbar, uint32_t bytes) {
    asm volatile("mbarrier.arrive.expect_tx.shared.b64 _, [%0], %1;"
                 :: "r"(mbar), "r"(bytes) : "memory");
}
__device__ __forceinline__ void mbar_wait(uint32_t mbar, uint32_t parity) {
    asm volatile(
        "{\n\t.reg .pred P;\n"
        "WL%=:\n\t"
        "mbarrier.try_wait.parity.shared.b64 P, [%0], %1;\n\t"
        "@P bra WD%=;\n\t"
        "bra WL%=;\n"
        "WD%=:\n\t}"
        :: "r"(mbar), "r"(parity) : "memory");
}
__device__ __forceinline__ void st_async_f32(uint32_t raddr, float v, uint32_t rmbar) {
    asm volatile(
        "st.async.weak.shared::cluster.mbarrier::complete_tx::bytes.f32 [%0], %1, [%2];"
        :: "r"(raddr), "f"(v), "r"(rmbar) : "memory");
}
__device__ __forceinline__ void cluster_arrive() {
    asm volatile("barrier.cluster.arrive.aligned;" ::: "memory");
}
__device__ __forceinline__ void cluster_wait() {
    asm volatile("barrier.cluster.wait.aligned;" ::: "memory");
}
__device__ __forceinline__ float fsig(float x) { return 1.f / (1.f + __expf(-x)); }

// packed f32x2 FMA (Blackwell) + packed smem loads
__device__ __forceinline__ uint64_t ffma2(uint64_t a, uint64_t b, uint64_t c) {
    uint64_t d;
    asm("fma.rn.f32x2 %0, %1, %2, %3;" : "=l"(d) : "l"(a), "l"(b), "l"(c));
    return d;
}
__device__ __forceinline__ void lds_v2u64(uint64_t& a, uint64_t& b, uint32_t addr) {
    asm volatile("ld.shared.v2.u64 {%0, %1}, [%2];" : "=l"(a), "=l"(b) : "r"(addr));
}
__device__ __forceinline__ uint64_t lds_u64(uint32_t addr) {
    uint64_t v;
    asm volatile("ld.shared.b64 %0, [%1];" : "=l"(v) : "r"(addr));
    return v;
}
__device__ __forceinline__ uint64_t pack2(float lo, float hi) {
    uint64_t d;
    asm("mov.b64 %0, {%1, %2};" : "=l"(d) : "f"(lo), "f"(hi));
    return d;
}
__device__ __forceinline__ float unpack_sum(uint64_t v) {
    float lo, hi;
    asm("mov.b64 {%0, %1}, %2;" : "=f"(lo), "=f"(hi) : "l"(v));
    return lo + hi;
}

// ---------------- precompute kernels ----------------
__global__ void k_w1csum(const float* __restrict__ W1) {
    int k = threadIdx.x;
    float s = 0.f;
    for (int j = 0; j < DK; j++) s += W1[(256 + j) * DK + k];
    g_W1csum[k] = s;
}

__global__ void __launch_bounds__(128) k_al(
    const int* __restrict__ qseq, const int* __restrict__ atseq,
    const float* __restrict__ corr, const float* __restrict__ e_w,
    const float* __restrict__ at_w, const float* __restrict__ W1,
    const float* __restrict__ b1)
{
    __shared__ float ev[8][DK], av[8][DK];
    const int s = blockIdx.x, bg = blockIdx.y, k = threadIdx.x;
    for (int bl = 0; bl < 8; bl++) {
        int bs = (bg * 8 + bl) * SS + s;
        ev[bl][k] = e_w[qseq[bs] * DK + k];
        av[bl][k] = at_w[atseq[bs] * DK + k];
    }
    __syncthreads();
    float acc[8];
    const float cs = g_W1csum[k], bb = b1[k];
    for (int bl = 0; bl < 8; bl++)
        acc[bl] = bb + corr[(bg * 8 + bl) * SS + s] * cs;
    for (int j = 0; j < DK; j++) {
        float we = W1[j * DK + k], wa = W1[(128 + j) * DK + k];
#pragma unroll
        for (int bl = 0; bl < 8; bl++) acc[bl] += ev[bl][j] * we + av[bl][j] * wa;
    }
    for (int bl = 0; bl < 8; bl++)
        g_AL[((bg * 8 + bl) * SS + s) * DK + k] = acc[bl];
}

__global__ void __launch_bounds__(128) k_pre(
    const int* __restrict__ qseq, const int* __restrict__ itseq,
    const float* __restrict__ e_w, const float* __restrict__ it_w,
    const float* __restrict__ W2, const float* __restrict__ b2,
    const float* __restrict__ W3, const float* __restrict__ b3,
    const float* __restrict__ W4, const float* __restrict__ b4,
    const float* __restrict__ W5, const float* __restrict__ b5)
{
    __shared__ float xp[8][DK], xi[8][DK], xc[8][DK], xe[8][DK];
    const int t = blockIdx.x, bg = blockIdx.y, k = threadIdx.x;
    for (int bl = 0; bl < 8; bl++) {
        int b = bg * 8 + bl;
        xp[bl][k] = (t > 0) ? g_AL[(b * SS + (t - 1)) * DK + k] : 0.f;
        xi[bl][k] = it_w[itseq[b * SS + t] * DK + k];
        xc[bl][k] = g_AL[(b * SS + t) * DK + k];
        xe[bl][k] = e_w[qseq[b * SS + t + 1] * DK + k];
    }
    __syncthreads();
    float a2[8], a3[8];
    {
        float v2 = b2[k], v3 = b3[k];
        for (int bl = 0; bl < 8; bl++) { a2[bl] = v2; a3[bl] = v3; }
    }
    for (int j = 0; j < DK; j++) {
        float w2 = W2[j * DK + k], w3 = W3[j * DK + k];
#pragma unroll
        for (int bl = 0; bl < 8; bl++) { float x = xp[bl][j]; a2[bl] += x * w2; a3[bl] += x * w3; }
    }
    for (int j = 0; j < DK; j++) {
        float w2 = W2[(128 + j) * DK + k], w3 = W3[(128 + j) * DK + k];
#pragma unroll
        for (int bl = 0; bl < 8; bl++) { float x = xi[bl][j]; a2[bl] += x * w2; a3[bl] += x * w3; }
    }
    for (int j = 0; j < DK; j++) {
        float w2 = W2[(256 + j) * DK + k], w3 = W3[(256 + j) * DK + k];
#pragma unroll
        for (int bl = 0; bl < 8; bl++) { float x = xc[bl][j]; a2[bl] += x * w2; a3[bl] += x * w3; }
    }
    for (int bl = 0; bl < 8; bl++) {
        int b = bg * 8 + bl;
        g_P23[(t * NB + b) * 256 + k] = a2[bl];
        g_P23[(t * NB + b) * 256 + 128 + k] = a3[bl];
    }
    float a4[8], a5[8];
    {
        float v4 = b4[k], v5 = b5[k];
        for (int bl = 0; bl < 8; bl++) { a4[bl] = v4; a5[bl] = v5; }
    }
    for (int j = 0; j < DK; j++) {
        float w4 = W4[(256 + j) * DK + k], w5 = W5[j * DK + k];
#pragma unroll
        for (int bl = 0; bl < 8; bl++) { a4[bl] += xi[bl][j] * w4; a5[bl] += xe[bl][j] * w5; }
    }
    for (int bl = 0; bl < 8; bl++) {
        int b = bg * 8 + bl;
        g_P4it[(t * NB + b) * DK + k] = a4[bl];
        g_P5[(t * NB + b) * DK + k] = a5[bl];
    }
}

// ---------------- main sequential kernel ----------------
// smem layout (float offsets):
#define F_MBAR  0          // 2 mbarriers (16 bytes)
#define F_W23DT 4          // [256][132]
#define F_W4HT  33796      // [128][132]
#define F_H     50692      // [16][128]
#define F_SLOT  52740      // [2][128][8]
#define F_HT    54788      // [128]
#define F_LG    54916      // [128]
#define F_ZB2   55044      // [512]  (two half-K partials of z2|z3)
#define F_GBP   55556      // [512]  (four quarter-K partials of g)
#define F_PT    56068      // [512]
#define F_QE    56580      // [16]
#define F_QN    56596      // [16]
#define SMEM_FLOATS 56612
#define SMEM_BYTES (SMEM_FLOATS * 4)

__global__ void __cluster_dims__(CSZ, 1, 1) __launch_bounds__(512, 1)
lpkt_main(const int* __restrict__ qseq, const float* __restrict__ qmat,
          const float* __restrict__ h0, const float* __restrict__ W2,
          const float* __restrict__ W3, const float* __restrict__ W4,
          float* __restrict__ out)
{
    extern __shared__ float sm[];
    float* W23dT = sm + F_W23DT;
    float* W4hT  = sm + F_W4HT;
    float* H     = sm + F_H;
    float* SLOT  = sm + F_SLOT;
    float* HT    = sm + F_HT;
    float* LG    = sm + F_LG;
    float* ZB2   = sm + F_ZB2;
    float* GBP   = sm + F_GBP;
    float* PT    = sm + F_PT;
    float* QE    = sm + F_QE;
    float* QN    = sm + F_QN;

    const int tid = threadIdx.x;
    const int k = tid & 127;
    const int q = tid >> 7;            // quarter-group 0..3
    const int batch = blockIdx.x / CSZ;
    const int rank = blockIdx.x % CSZ;
    const int n0 = rank * 13;

    const uint32_t smbase = smem_u32(sm);
    const uint32_t mbar_local = smbase;

    if (tid == 0) { mbar_init(mbar_local, 1); mbar_init(mbar_local + 8, 1); }

    // --- W4 mid-chunk quarter into packed registers (loop-invariant) ---
    uint64_t w4r[16];
#pragma unroll
    for (int j = 0; j < 16; j++) {
        float lo = W4[(128 + q * 32 + 2 * j) * DK + k];
        float hi = W4[(128 + q * 32 + 2 * j + 1) * DK + k];
        w4r[j] = pack2(lo, hi);
    }

    // --- stage weights into smem ---
    for (int idx = tid; idx < 256 * 128; idx += 512) {
        int col = idx & 255, j = idx >> 8;
        float v = (col < 128) ? W2[(384 + j) * DK + col]
                              : W3[(384 + j) * DK + (col - 128)];
        W23dT[col * 132 + j] = v;
    }
    for (int idx = tid; idx < 128 * 128; idx += 512) {
        int c = idx & 127, j = idx >> 7;
        W4hT[c * 132 + j] = W4[j * DK + c];
    }
    for (int idx = tid; idx < RPC * 128; idx += 512) {
        int r = idx >> 7, c = idx & 127;
        int n = n0 + r;
        H[idx] = (r < 13 && n < NC) ? h0[n * DK + c] : 0.f;
    }
    {
        int q0 = qseq[batch * SS];
        if (tid < NC) ZB2[tid] = qmat[q0 * NC + tid];
    }
    __syncthreads();
    if (tid < 128) {
        float a0 = 0.f, a1 = 0.f;
        for (int n = 0; n < NC; n += 2) {
            a0 += ZB2[n] * h0[n * DK + k];
            a1 += ZB2[n + 1] * h0[(n + 1) * DK + k];
        }
        HT[k] = a0 + a1;
    }
    __syncthreads();
    cluster_arrive();          // one-time: mbarrier init visible cluster-wide
    cluster_wait();

    uint32_t rbase[CSZ];
#pragma unroll
    for (int r = 0; r < CSZ; r++) rbase[r] = mapa_u32(smbase, (uint32_t)r);

    const uint32_t wb_gemm = smbase + (uint32_t)((F_W4HT + k * 132) * 4);
    const uint32_t hb_gemm = smbase + (uint32_t)((F_H + q * 4 * 128) * 4);
    const int o = tid & 255, half = tid >> 8;
    const uint32_t wz = smbase + (uint32_t)((F_W23DT + o * 132 + half * 64) * 4);
    const uint32_t hz = smbase + (uint32_t)((F_HT + half * 64) * 4);
    const uint32_t lgb = smbase + (uint32_t)((F_LG + q * 32) * 4);

    int phase[2] = {0, 0};

    for (int t = 0; t < SS - 1; t++) {
        const int pn = (t + 1) & 1;
        if (tid == 0) mbar_expect(mbar_local + pn * 8, CSZ * 128 * 4);

        // ---- prefetch globals (hidden under GEMM) ----
        float p23 = (tid < 256) ? g_P23[(t * NB + batch) * 256 + tid] : 0.f;
        float p4 = (q == 0) ? g_P4it[(t * NB + batch) * DK + k] : 0.f;
        if (tid < RPC) {
            int n = n0 + tid;
            bool valid = (tid < 13) && (n < NC);
            int qa = qseq[batch * SS + t];
            int qb = qseq[batch * SS + t + 1];
            QE[tid] = valid ? qmat[qa * NC + n] : 0.f;
            QN[tid] = valid ? qmat[qb * NC + n] : 0.f;
        }

        // ---- big GEMM: 4 rows x 128 via packed f32x2 (pre-wait filler) ----
        uint64_t acc2[4] = {0ull, 0ull, 0ull, 0ull};
#pragma unroll
        for (int j4 = 0; j4 < 32; j4++) {
            uint64_t w0, w1;
            lds_v2u64(w0, w1, wb_gemm + j4 * 16);
#pragma unroll
            for (int r = 0; r < 4; r++) {
                uint64_t hp0, hp1;
                lds_v2u64(hp0, hp1, hb_gemm + r * 512 + j4 * 16);
                acc2[r] = ffma2(w0, hp0, acc2[r]);
                acc2[r] = ffma2(w1, hp1, acc2[r]);
            }
        }

        // ---- wait for incoming h_tilde partials, sum 8 slots ----
        if (t > 0) {
            const int p = t & 1;
            mbar_wait(mbar_local + p * 8, phase[p]);
            phase[p] ^= 1;
            if (tid < 128) {
                const float4* s4 = (const float4*)(SLOT + p * 1024 + tid * 8);
                float4 a = s4[0], b = s4[1];
                float s = ((a.x + a.y) + (a.z + a.w)) + ((b.x + b.y) + (b.z + b.w));
                HT[tid] = s;
                if (rank == 0) g_HT[((t - 1) * NB + batch) * DK + tid] = s;
            }
        }
        __syncthreads();

        // ---- z2/z3 GEMV: 256 outputs, K split in halves, packed FMA ----
        {
            uint64_t a0 = 0ull, a1 = 0ull;
#pragma unroll
            for (int j4 = 0; j4 < 16; j4++) {
                uint64_t w0, w1, x0, x1;
                lds_v2u64(w0, w1, wz + j4 * 16);
                lds_v2u64(x0, x1, hz + j4 * 16);
                a0 = ffma2(w0, x0, a0);
                a1 = ffma2(w1, x1, a1);
            }
            ZB2[tid] = p23 + unpack_sum(a0) + unpack_sum(a1);
        }
        __syncthreads();
        if (tid < 128) {
            float z2 = ZB2[k] + ZB2[256 + k];
            float z3 = ZB2[128 + k] + ZB2[384 + k];
            LG[k] = fsig(z3) * fsig(2.f * z2);   // (tanh+1)/2 == sigmoid(2x)
        }
        __syncthreads();

        // ---- g partials: quarter-K from register-resident packed W4 ----
        {
            uint64_t s0 = 0ull, s1 = 0ull;
#pragma unroll
            for (int j = 0; j < 16; j += 2) {
                s0 = ffma2(w4r[j],     lds_u64(lgb + j * 8),       s0);
                s1 = ffma2(w4r[j + 1], lds_u64(lgb + (j + 1) * 8), s1);
            }
            GBP[tid] = p4 + unpack_sum(s0) + unpack_sum(s1);
        }
        __syncthreads();

        // ---- finish gamma, update H, partial h_tilde ----
        {
            float lgk = LG[k];
            float gval = (GBP[k] + GBP[128 + k]) + (GBP[256 + k] + GBP[384 + k]);
            float pa = 0.f, pb = 0.f;
#pragma unroll
            for (int r = 0; r < 4; r++) {
                int row = q * 4 + r;
                float hold = H[row * DK + k];
                float hnew = QE[row] * lgk + fsig(unpack_sum(acc2[r]) + gval) * hold;
                H[row * DK + k] = hnew;
                if (r & 1) pb += QN[row] * hnew;
                else       pa += QN[row] * hnew;
            }
            PT[tid] = pa + pb;
        }
        __syncthreads();

        // ---- push combined partial to all 8 peers ----
        if (tid < 128) {
            float c = (PT[tid] + PT[128 + tid]) + (PT[256 + tid] + PT[384 + tid]);
            const uint32_t soff = (uint32_t)((F_SLOT + pn * 1024 + tid * 8 + rank) * 4);
#pragma unroll
            for (int r = 0; r < CSZ; r++)
                st_async_f32(rbase[r] + soff, c, rbase[r] + (uint32_t)(pn * 8));
        }
    }

    // ---- final exchange: h_tilde after last update (t index 126) ----
    {
        mbar_wait(mbar_local + 8, phase[1]);
        if (rank == 0 && tid < 128) {
            const float4* s4 = (const float4*)(SLOT + 1024 + tid * 8);
            float4 a = s4[0], b = s4[1];
            float s = ((a.x + a.y) + (a.z + a.w)) + ((b.x + b.y) + (b.z + b.w));
            g_HT[(126 * NB + batch) * DK + tid] = s;
        }
    }
}

// ---------------- prediction post-pass (fully parallel) ----------------
__global__ void __launch_bounds__(128) k_pred(
    const float* __restrict__ W5, float* __restrict__ out)
{
    __shared__ float ht[DK];
    __shared__ float red[DK];
    const int t = blockIdx.x, b = blockIdx.y, k = threadIdx.x;
    ht[k] = g_HT[(t * NB + b) * DK + k];
    float acc0 = g_P5[(t * NB + b) * DK + k];
    float acc1 = 0.f, acc2 = 0.f, acc3 = 0.f;
    __syncthreads();
    const float* w5p = W5 + 128 * DK + k;
#pragma unroll 8
    for (int j = 0; j < DK; j += 4) {
        acc0 += ht[j]     * w5p[j * DK];
        acc1 += ht[j + 1] * w5p[(j + 1) * DK];
        acc2 += ht[j + 2] * w5p[(j + 2) * DK];
        acc3 += ht[j + 3] * w5p[(j + 3) * DK];
    }
    red[k] = fsig((acc0 + acc1) + (acc2 + acc3));
    __syncthreads();
    if (k < 32) {
        float s = red[k] + red[k + 32] + red[k + 64] + red[k + 96];
#pragma unroll
        for (int o = 16; o > 0; o >>= 1) s += __shfl_down_sync(0xffffffffu, s, o);
        if (k == 0) {
            out[b * SS + t + 1] = s * (1.f / 128.f);
            if (t == 0) out[b * SS] = 0.f;
        }
    }
}

// ---------------- launcher ----------------
extern "C" void kernel_launch(void* const* d_in, const int* in_sizes, int n_in,
                              void* d_out, int out_size)
{
    const int* qseq   = (const int*)d_in[0];
    const int* atseq  = (const int*)d_in[1];
    const int* itseq  = (const int*)d_in[2];
    const float* corr = (const float*)d_in[3];
    const float* qmat = (const float*)d_in[4];
    const float* h0   = (const float*)d_in[5];
    const float* e_w  = (const float*)d_in[6];
    const float* at_w = (const float*)d_in[7];
    const float* it_w = (const float*)d_in[8];
    const float* W1 = (const float*)d_in[9];
    const float* b1 = (const float*)d_in[10];
    const float* W2 = (const float*)d_in[11];
    const float* b2 = (const float*)d_in[12];
    const float* W3 = (const float*)d_in[13];
    const float* b3 = (const float*)d_in[14];
    const float* W4 = (const float*)d_in[15];
    const float* b4 = (const float*)d_in[16];
    const float* W5 = (const float*)d_in[17];
    const float* b5 = (const float*)d_in[18];
    float* out = (float*)d_out;

    cudaFuncSetAttribute(lpkt_main, cudaFuncAttributeMaxDynamicSharedMemorySize,
                         SMEM_BYTES);

    k_w1csum<<<1, 128>>>(W1);
    k_al<<<dim3(SS, 2), 128>>>(qseq, atseq, corr, e_w, at_w, W1, b1);
    k_pre<<<dim3(SS - 1, 2), 128>>>(qseq, itseq, e_w, it_w,
                                    W2, b2, W3, b3, W4, b4, W5, b5);
    lpkt_main<<<NB * CSZ, 512, SMEM_BYTES>>>(qseq, qmat, h0, W2, W3, W4, out);
    k_pred<<<dim3(SS - 1, NB), 128>>>(W5, out);
}